// round 5
// baseline (speedup 1.0000x reference)
#include <cuda_runtime.h>
#include <cuda_bf16.h>

// Problem constants
#define BB 2
#define LL 2048
#define DD 1024
#define HH 16
#define HD 64

// Scratch (device globals — no allocation allowed)
__device__ float g_Q[BB*HH*LL*HD];    // (B,H,L,HD)
__device__ float g_K[BB*HH*LL*HD];
__device__ float g_V[BB*HH*LL*HD];
__device__ float g_CTX[BB*LL*DD];     // concat layout (B,L,H*HD)

// ---------------------------------------------------------------------------
// Kernel 1: fused QKV projection.
// grid = (BL/64, H, 3), block = 128. Tile 64x64, BK=16, 8x4 microtile/thread.
// q[b,h,l,e] = sum_d x[b,l,d] * W[h,d,e] + bias[h,e]
// ---------------------------------------------------------------------------
__global__ __launch_bounds__(128) void qkv_kernel(
    const float* __restrict__ x,
    const float* __restrict__ Wq, const float* __restrict__ bq,
    const float* __restrict__ Wk, const float* __restrict__ bk,
    const float* __restrict__ Wv, const float* __restrict__ bv)
{
    const int h   = blockIdx.y;
    const int mat = blockIdx.z;

    const float* W;  const float* bias;  float* out;
    if (mat == 0)      { W = Wq + h*DD*HD; bias = bq + h*HD; out = g_Q; }
    else if (mat == 1) { W = Wk + h*DD*HD; bias = bk + h*HD; out = g_K; }
    else               { W = Wv + h*DD*HD; bias = bv + h*HD; out = g_V; }

    __shared__ float As[16][65];   // transposed A tile, padded
    __shared__ float Bs[16][64];

    const int tid = threadIdx.x;
    const int tx  = tid & 15;      // 16 col groups * 4 = 64
    const int ty  = tid >> 4;      // 8 row groups * 8 = 64
    const int row0 = blockIdx.x * 64;

    float acc[8][4];
    #pragma unroll
    for (int i = 0; i < 8; i++)
        #pragma unroll
        for (int j = 0; j < 4; j++) acc[i][j] = 0.f;

    for (int k0 = 0; k0 < DD; k0 += 16) {
        // A tile: 64 rows x 16 k (256 float4, 2 per thread), stored transposed
        #pragma unroll
        for (int i = 0; i < 2; i++) {
            int idx = tid + i*128;
            int r   = idx >> 2;
            int kc  = (idx & 3) * 4;
            float4 v = *(const float4*)&x[(row0 + r)*DD + k0 + kc];
            As[kc+0][r] = v.x; As[kc+1][r] = v.y; As[kc+2][r] = v.z; As[kc+3][r] = v.w;
        }
        // B tile: 16 k x 64 n
        #pragma unroll
        for (int i = 0; i < 2; i++) {
            int idx = tid + i*128;
            int kr  = idx >> 4;
            int nc  = (idx & 15) * 4;
            *(float4*)&Bs[kr][nc] = *(const float4*)&W[(k0 + kr)*HD + nc];
        }
        __syncthreads();
        #pragma unroll
        for (int kk = 0; kk < 16; kk++) {
            float a[8], bb[4];
            #pragma unroll
            for (int i = 0; i < 8; i++) a[i] = As[kk][ty*8 + i];
            #pragma unroll
            for (int j = 0; j < 4; j++) bb[j] = Bs[kk][tx*4 + j];
            #pragma unroll
            for (int i = 0; i < 8; i++)
                #pragma unroll
                for (int j = 0; j < 4; j++)
                    acc[i][j] += a[i] * bb[j];
        }
        __syncthreads();
    }

    // Write to (B,H,L,HD) layout
    #pragma unroll
    for (int i = 0; i < 8; i++) {
        int r = row0 + ty*8 + i;
        int b = r >> 11;           // L = 2048
        int l = r & 2047;
        float* orow = out + ((size_t)(b*HH + h)*LL + l)*HD;
        #pragma unroll
        for (int j = 0; j < 4; j++) {
            int n = tx*4 + j;
            orow[n] = acc[i][j] + bias[n];
        }
    }
}

// ---------------------------------------------------------------------------
// Kernel 2: flash attention, 1 thread = 1 query row.
// grid = (L/128, B*H), block = 128. K/V staged as 64-key tiles in smem.
// Online softmax with lazy rescale. Writes ctx directly in concat layout.
// ---------------------------------------------------------------------------
__global__ __launch_bounds__(128) void attn_kernel(const int* __restrict__ mask)
{
    const int bh = blockIdx.y;
    const int b  = bh >> 4;             // H = 16
    const int q  = blockIdx.x * 128 + threadIdx.x;
    const int h  = bh & 15;

    const float4* Qrow  = (const float4*)(g_Q + (((size_t)bh)*LL + q)*HD);
    const float4* Kbase = (const float4*)(g_K + ((size_t)bh)*LL*HD);
    const float4* Vbase = (const float4*)(g_V + ((size_t)bh)*LL*HD);

    __shared__ float4 Ks[64*16];        // 64 keys x 64 floats
    __shared__ float4 Vs[64*16];
    __shared__ int    ms[64];

    float4 qv[16];
    #pragma unroll
    for (int i = 0; i < 16; i++) qv[i] = Qrow[i];

    float o[64];
    #pragma unroll
    for (int e = 0; e < 64; e++) o[e] = 0.f;
    float m = -1e30f, l = 0.f;

    for (int kt = 0; kt < LL/64; kt++) {
        __syncthreads();
        #pragma unroll
        for (int i = 0; i < 8; i++) {
            int idx = threadIdx.x + i*128;          // 1024 float4 per tile
            Ks[idx] = Kbase[kt*64*16 + idx];
            Vs[idx] = Vbase[kt*64*16 + idx];
        }
        if (threadIdx.x < 64) ms[threadIdx.x] = mask[b*LL + kt*64 + threadIdx.x];
        __syncthreads();

        for (int j = 0; j < 64; j++) {
            const float4* kr = &Ks[j*16];
            float s = 0.f;
            #pragma unroll
            for (int e = 0; e < 16; e++) {
                float4 kk = kr[e];
                s += qv[e].x*kk.x + qv[e].y*kk.y + qv[e].z*kk.z + qv[e].w*kk.w;
            }
            s *= 0.125f;                           // 1/sqrt(64)
            if (ms[j] == 0) s = -1e9f;

            if (s > m) {                           // lazy rescale (rare after warmup)
                float corr = __expf(m - s);
                l *= corr;
                #pragma unroll
                for (int e = 0; e < 64; e++) o[e] *= corr;
                m = s;
            }
            float p = __expf(s - m);
            l += p;
            const float4* vr = &Vs[j*16];
            #pragma unroll
            for (int e = 0; e < 16; e++) {
                float4 vv = vr[e];
                o[4*e+0] += p*vv.x; o[4*e+1] += p*vv.y;
                o[4*e+2] += p*vv.z; o[4*e+3] += p*vv.w;
            }
        }
    }

    const float inv = 1.0f / l;
    float* crow = g_CTX + ((size_t)(b*LL + q))*DD + h*HD;
    #pragma unroll
    for (int e = 0; e < 64; e++) crow[e] = o[e] * inv;
}

// ---------------------------------------------------------------------------
// Kernel 3: output projection. out = ctx @ Wo + bo.
// M=4096, N=1024, K=1024. Same 64x64/BK16 tiling as kernel 1.
// ---------------------------------------------------------------------------
__global__ __launch_bounds__(128) void out_proj_kernel(
    const float* __restrict__ Wo, const float* __restrict__ bo,
    float* __restrict__ out)
{
    __shared__ float As[16][65];
    __shared__ float Bs[16][64];

    const int tid = threadIdx.x;
    const int tx  = tid & 15;
    const int ty  = tid >> 4;
    const int row0 = blockIdx.x * 64;
    const int n0   = blockIdx.y * 64;

    float acc[8][4];
    #pragma unroll
    for (int i = 0; i < 8; i++)
        #pragma unroll
        for (int j = 0; j < 4; j++) acc[i][j] = 0.f;

    for (int k0 = 0; k0 < DD; k0 += 16) {
        #pragma unroll
        for (int i = 0; i < 2; i++) {
            int idx = tid + i*128;
            int r   = idx >> 2;
            int kc  = (idx & 3) * 4;
            float4 v = *(const float4*)&g_CTX[(size_t)(row0 + r)*DD + k0 + kc];
            As[kc+0][r] = v.x; As[kc+1][r] = v.y; As[kc+2][r] = v.z; As[kc+3][r] = v.w;
        }
        #pragma unroll
        for (int i = 0; i < 2; i++) {
            int idx = tid + i*128;
            int kr  = idx >> 4;
            int nc  = (idx & 15) * 4;
            *(float4*)&Bs[kr][nc] = *(const float4*)&Wo[(size_t)(k0 + kr)*DD + n0 + nc];
        }
        __syncthreads();
        #pragma unroll
        for (int kk = 0; kk < 16; kk++) {
            float a[8], bb[4];
            #pragma unroll
            for (int i = 0; i < 8; i++) a[i] = As[kk][ty*8 + i];
            #pragma unroll
            for (int j = 0; j < 4; j++) bb[j] = Bs[kk][tx*4 + j];
            #pragma unroll
            for (int i = 0; i < 8; i++)
                #pragma unroll
                for (int j = 0; j < 4; j++)
                    acc[i][j] += a[i] * bb[j];
        }
        __syncthreads();
    }

    #pragma unroll
    for (int i = 0; i < 8; i++) {
        int r = row0 + ty*8 + i;
        float* orow = out + (size_t)r*DD + n0;
        #pragma unroll
        for (int j = 0; j < 4; j++) {
            int n = tx*4 + j;
            orow[n] = acc[i][j] + bo[n0 + n];
        }
    }
}

// ---------------------------------------------------------------------------
extern "C" void kernel_launch(void* const* d_in, const int* in_sizes, int n_in,
                              void* d_out, int out_size)
{
    const float* x    = (const float*)d_in[0];
    const int*   mask = (const int*)  d_in[1];
    const float* Wq   = (const float*)d_in[2];
    const float* bq   = (const float*)d_in[3];
    const float* Wk   = (const float*)d_in[4];
    const float* bk   = (const float*)d_in[5];
    const float* Wv   = (const float*)d_in[6];
    const float* bv   = (const float*)d_in[7];
    const float* Wo   = (const float*)d_in[8];
    const float* bo   = (const float*)d_in[9];
    float* out = (float*)d_out;

    dim3 g1(BB*LL/64, HH, 3);            // (64, 16, 3)
    qkv_kernel<<<g1, 128>>>(x, Wq, bq, Wk, bk, Wv, bv);

    dim3 g2(LL/128, BB*HH);              // (16, 32)
    attn_kernel<<<g2, 128>>>(mask);

    dim3 g3(BB*LL/64, DD/64);            // (64, 16)
    out_proj_kernel<<<g3, 128>>>(Wo, bo, out);
}

// round 7
// speedup vs baseline: 1.0557x; 1.0557x over previous
#include <cuda_runtime.h>
#include <cuda_bf16.h>

// Problem constants
#define BB 2
#define LL 2048
#define DD 1024
#define HH 16
#define HD 64

// Scratch (device globals — no allocation allowed)
__device__ float g_Q[BB*HH*LL*HD];    // (B,H,L,HD)
__device__ float g_K[BB*HH*LL*HD];
__device__ float g_V[BB*HH*LL*HD];
__device__ float g_CTX[BB*LL*DD];     // concat layout (B,L,H*HD)

// ---------------------------------------------------------------------------
// Kernel 1: fused QKV projection.
// grid = (BL/64, H, 3), block = 128. Tile 64x64, BK=16, 8x4 microtile/thread.
// q[b,h,l,e] = sum_d x[b,l,d] * W[h,d,e] + bias[h,e]
// ---------------------------------------------------------------------------
__global__ __launch_bounds__(128) void qkv_kernel(
    const float* __restrict__ x,
    const float* __restrict__ Wq, const float* __restrict__ bq,
    const float* __restrict__ Wk, const float* __restrict__ bk,
    const float* __restrict__ Wv, const float* __restrict__ bv)
{
    const int h   = blockIdx.y;
    const int mat = blockIdx.z;

    const float* W;  const float* bias;  float* out;
    if (mat == 0)      { W = Wq + h*DD*HD; bias = bq + h*HD; out = g_Q; }
    else if (mat == 1) { W = Wk + h*DD*HD; bias = bk + h*HD; out = g_K; }
    else               { W = Wv + h*DD*HD; bias = bv + h*HD; out = g_V; }

    __shared__ float As[16][65];   // transposed A tile, padded
    __shared__ float Bs[16][64];

    const int tid = threadIdx.x;
    const int tx  = tid & 15;      // 16 col groups * 4 = 64
    const int ty  = tid >> 4;      // 8 row groups * 8 = 64
    const int row0 = blockIdx.x * 64;

    float acc[8][4];
    #pragma unroll
    for (int i = 0; i < 8; i++)
        #pragma unroll
        for (int j = 0; j < 4; j++) acc[i][j] = 0.f;

    for (int k0 = 0; k0 < DD; k0 += 16) {
        // A tile: 64 rows x 16 k (256 float4, 2 per thread), stored transposed
        #pragma unroll
        for (int i = 0; i < 2; i++) {
            int idx = tid + i*128;
            int r   = idx >> 2;
            int kc  = (idx & 3) * 4;
            float4 v = *(const float4*)&x[(row0 + r)*DD + k0 + kc];
            As[kc+0][r] = v.x; As[kc+1][r] = v.y; As[kc+2][r] = v.z; As[kc+3][r] = v.w;
        }
        // B tile: 16 k x 64 n
        #pragma unroll
        for (int i = 0; i < 2; i++) {
            int idx = tid + i*128;
            int kr  = idx >> 4;
            int nc  = (idx & 15) * 4;
            *(float4*)&Bs[kr][nc] = *(const float4*)&W[(k0 + kr)*HD + nc];
        }
        __syncthreads();
        #pragma unroll
        for (int kk = 0; kk < 16; kk++) {
            float a[8], bb[4];
            #pragma unroll
            for (int i = 0; i < 8; i++) a[i] = As[kk][ty*8 + i];
            #pragma unroll
            for (int j = 0; j < 4; j++) bb[j] = Bs[kk][tx*4 + j];
            #pragma unroll
            for (int i = 0; i < 8; i++)
                #pragma unroll
                for (int j = 0; j < 4; j++)
                    acc[i][j] += a[i] * bb[j];
        }
        __syncthreads();
    }

    // Write to (B,H,L,HD) layout
    #pragma unroll
    for (int i = 0; i < 8; i++) {
        int r = row0 + ty*8 + i;
        int b = r >> 11;           // L = 2048
        int l = r & 2047;
        float* orow = out + ((size_t)(b*HH + h)*LL + l)*HD;
        #pragma unroll
        for (int j = 0; j < 4; j++) {
            int n = tx*4 + j;
            orow[n] = acc[i][j] + bias[n];
        }
    }
}

// ---------------------------------------------------------------------------
// Kernel 2: flash attention, 1 thread = 1 query row.
// grid = (L/128, B*H), block = 128. K/V staged as 64-key tiles in smem.
// Online softmax with lazy rescale. Writes ctx directly in concat layout.
// ---------------------------------------------------------------------------
__global__ __launch_bounds__(128) void attn_kernel(const int* __restrict__ mask)
{
    const int bh = blockIdx.y;
    const int b  = bh >> 4;             // H = 16
    const int q  = blockIdx.x * 128 + threadIdx.x;
    const int h  = bh & 15;

    const float4* Qrow  = (const float4*)(g_Q + (((size_t)bh)*LL + q)*HD);
    const float4* Kbase = (const float4*)(g_K + ((size_t)bh)*LL*HD);
    const float4* Vbase = (const float4*)(g_V + ((size_t)bh)*LL*HD);

    __shared__ float4 Ks[64*16];        // 64 keys x 64 floats
    __shared__ float4 Vs[64*16];
    __shared__ int    ms[64];

    float4 qv[16];
    #pragma unroll
    for (int i = 0; i < 16; i++) qv[i] = Qrow[i];

    float o[64];
    #pragma unroll
    for (int e = 0; e < 64; e++) o[e] = 0.f;
    float m = -1e30f, l = 0.f;

    for (int kt = 0; kt < LL/64; kt++) {
        __syncthreads();
        #pragma unroll
        for (int i = 0; i < 8; i++) {
            int idx = threadIdx.x + i*128;          // 1024 float4 per tile
            Ks[idx] = Kbase[kt*64*16 + idx];
            Vs[idx] = Vbase[kt*64*16 + idx];
        }
        if (threadIdx.x < 64) ms[threadIdx.x] = mask[b*LL + kt*64 + threadIdx.x];
        __syncthreads();

        for (int j = 0; j < 64; j++) {
            const float4* kr = &Ks[j*16];
            float s = 0.f;
            #pragma unroll
            for (int e = 0; e < 16; e++) {
                float4 kk = kr[e];
                s += qv[e].x*kk.x + qv[e].y*kk.y + qv[e].z*kk.z + qv[e].w*kk.w;
            }
            s *= 0.125f;                           // 1/sqrt(64)
            if (ms[j] == 0) s = -1e9f;

            if (s > m) {                           // lazy rescale (rare after warmup)
                float corr = __expf(m - s);
                l *= corr;
                #pragma unroll
                for (int e = 0; e < 64; e++) o[e] *= corr;
                m = s;
            }
            float p = __expf(s - m);
            l += p;
            const float4* vr = &Vs[j*16];
            #pragma unroll
            for (int e = 0; e < 16; e++) {
                float4 vv = vr[e];
                o[4*e+0] += p*vv.x; o[4*e+1] += p*vv.y;
                o[4*e+2] += p*vv.z; o[4*e+3] += p*vv.w;
            }
        }
    }

    const float inv = 1.0f / l;
    float* crow = g_CTX + ((size_t)(b*LL + q))*DD + h*HD;
    #pragma unroll
    for (int e = 0; e < 64; e++) crow[e] = o[e] * inv;
}

// ---------------------------------------------------------------------------
// Kernel 3: output projection. out = ctx @ Wo + bo.
// M=4096, N=1024, K=1024. Same 64x64/BK16 tiling as kernel 1.
// ---------------------------------------------------------------------------
__global__ __launch_bounds__(128) void out_proj_kernel(
    const float* __restrict__ Wo, const float* __restrict__ bo,
    float* __restrict__ out)
{
    __shared__ float As[16][65];
    __shared__ float Bs[16][64];

    const int tid = threadIdx.x;
    const int tx  = tid & 15;
    const int ty  = tid >> 4;
    const int row0 = blockIdx.x * 64;
    const int n0   = blockIdx.y * 64;

    float acc[8][4];
    #pragma unroll
    for (int i = 0; i < 8; i++)
        #pragma unroll
        for (int j = 0; j < 4; j++) acc[i][j] = 0.f;

    for (int k0 = 0; k0 < DD; k0 += 16) {
        #pragma unroll
        for (int i = 0; i < 2; i++) {
            int idx = tid + i*128;
            int r   = idx >> 2;
            int kc  = (idx & 3) * 4;
            float4 v = *(const float4*)&g_CTX[(size_t)(row0 + r)*DD + k0 + kc];
            As[kc+0][r] = v.x; As[kc+1][r] = v.y; As[kc+2][r] = v.z; As[kc+3][r] = v.w;
        }
        #pragma unroll
        for (int i = 0; i < 2; i++) {
            int idx = tid + i*128;
            int kr  = idx >> 4;
            int nc  = (idx & 15) * 4;
            *(float4*)&Bs[kr][nc] = *(const float4*)&Wo[(size_t)(k0 + kr)*DD + n0 + nc];
        }
        __syncthreads();
        #pragma unroll
        for (int kk = 0; kk < 16; kk++) {
            float a[8], bb[4];
            #pragma unroll
            for (int i = 0; i < 8; i++) a[i] = As[kk][ty*8 + i];
            #pragma unroll
            for (int j = 0; j < 4; j++) bb[j] = Bs[kk][tx*4 + j];
            #pragma unroll
            for (int i = 0; i < 8; i++)
                #pragma unroll
                for (int j = 0; j < 4; j++)
                    acc[i][j] += a[i] * bb[j];
        }
        __syncthreads();
    }

    #pragma unroll
    for (int i = 0; i < 8; i++) {
        int r = row0 + ty*8 + i;
        float* orow = out + (size_t)r*DD + n0;
        #pragma unroll
        for (int j = 0; j < 4; j++) {
            int n = tx*4 + j;
            orow[n] = acc[i][j] + bo[n0 + n];
        }
    }
}

// ---------------------------------------------------------------------------
extern "C" void kernel_launch(void* const* d_in, const int* in_sizes, int n_in,
                              void* d_out, int out_size)
{
    const float* x    = (const float*)d_in[0];
    const int*   mask = (const int*)  d_in[1];
    const float* Wq   = (const float*)d_in[2];
    const float* bq   = (const float*)d_in[3];
    const float* Wk   = (const float*)d_in[4];
    const float* bk   = (const float*)d_in[5];
    const float* Wv   = (const float*)d_in[6];
    const float* bv   = (const float*)d_in[7];
    const float* Wo   = (const float*)d_in[8];
    const float* bo   = (const float*)d_in[9];
    float* out = (float*)d_out;

    dim3 g1(BB*LL/64, HH, 3);            // (64, 16, 3)
    qkv_kernel<<<g1, 128>>>(x, Wq, bq, Wk, bk, Wv, bv);

    dim3 g2(LL/128, BB*HH);              // (16, 32)
    attn_kernel<<<g2, 128>>>(mask);

    dim3 g3(BB*LL/64, DD/64);            // (64, 16)
    out_proj_kernel<<<g3, 128>>>(Wo, bo, out);
}

// round 8
// speedup vs baseline: 1.0559x; 1.0002x over previous
#include <cuda_runtime.h>
#include <cuda_bf16.h>

// Problem constants
#define BB 2
#define LL 2048
#define DD 1024
#define HH 16
#define HD 64

// Scratch (device globals — no allocation allowed)
__device__ float g_Q[BB*HH*LL*HD];    // (B,H,L,HD)
__device__ float g_K[BB*HH*LL*HD];
__device__ float g_V[BB*HH*LL*HD];
__device__ float g_CTX[BB*LL*DD];     // concat layout (B,L,H*HD)

// ---------------------------------------------------------------------------
// Kernel 1: fused QKV projection.
// grid = (BL/64, H, 3), block = 128. Tile 64x64, BK=16, 8x4 microtile/thread.
// q[b,h,l,e] = sum_d x[b,l,d] * W[h,d,e] + bias[h,e]
// ---------------------------------------------------------------------------
__global__ __launch_bounds__(128) void qkv_kernel(
    const float* __restrict__ x,
    const float* __restrict__ Wq, const float* __restrict__ bq,
    const float* __restrict__ Wk, const float* __restrict__ bk,
    const float* __restrict__ Wv, const float* __restrict__ bv)
{
    const int h   = blockIdx.y;
    const int mat = blockIdx.z;

    const float* W;  const float* bias;  float* out;
    if (mat == 0)      { W = Wq + h*DD*HD; bias = bq + h*HD; out = g_Q; }
    else if (mat == 1) { W = Wk + h*DD*HD; bias = bk + h*HD; out = g_K; }
    else               { W = Wv + h*DD*HD; bias = bv + h*HD; out = g_V; }

    __shared__ float As[16][65];   // transposed A tile, padded
    __shared__ float Bs[16][64];

    const int tid = threadIdx.x;
    const int tx  = tid & 15;      // 16 col groups * 4 = 64
    const int ty  = tid >> 4;      // 8 row groups * 8 = 64
    const int row0 = blockIdx.x * 64;

    float acc[8][4];
    #pragma unroll
    for (int i = 0; i < 8; i++)
        #pragma unroll
        for (int j = 0; j < 4; j++) acc[i][j] = 0.f;

    for (int k0 = 0; k0 < DD; k0 += 16) {
        // A tile: 64 rows x 16 k (256 float4, 2 per thread), stored transposed
        #pragma unroll
        for (int i = 0; i < 2; i++) {
            int idx = tid + i*128;
            int r   = idx >> 2;
            int kc  = (idx & 3) * 4;
            float4 v = *(const float4*)&x[(row0 + r)*DD + k0 + kc];
            As[kc+0][r] = v.x; As[kc+1][r] = v.y; As[kc+2][r] = v.z; As[kc+3][r] = v.w;
        }
        // B tile: 16 k x 64 n
        #pragma unroll
        for (int i = 0; i < 2; i++) {
            int idx = tid + i*128;
            int kr  = idx >> 4;
            int nc  = (idx & 15) * 4;
            *(float4*)&Bs[kr][nc] = *(const float4*)&W[(k0 + kr)*HD + nc];
        }
        __syncthreads();
        #pragma unroll
        for (int kk = 0; kk < 16; kk++) {
            float a[8], bb[4];
            #pragma unroll
            for (int i = 0; i < 8; i++) a[i] = As[kk][ty*8 + i];
            #pragma unroll
            for (int j = 0; j < 4; j++) bb[j] = Bs[kk][tx*4 + j];
            #pragma unroll
            for (int i = 0; i < 8; i++)
                #pragma unroll
                for (int j = 0; j < 4; j++)
                    acc[i][j] += a[i] * bb[j];
        }
        __syncthreads();
    }

    // Write to (B,H,L,HD) layout
    #pragma unroll
    for (int i = 0; i < 8; i++) {
        int r = row0 + ty*8 + i;
        int b = r >> 11;           // L = 2048
        int l = r & 2047;
        float* orow = out + ((size_t)(b*HH + h)*LL + l)*HD;
        #pragma unroll
        for (int j = 0; j < 4; j++) {
            int n = tx*4 + j;
            orow[n] = acc[i][j] + bias[n];
        }
    }
}

// ---------------------------------------------------------------------------
// Kernel 2: flash attention, 1 thread = 1 query row.
// grid = (L/128, B*H), block = 128. K/V staged as 64-key tiles in smem.
// Online softmax with lazy rescale. Writes ctx directly in concat layout.
// ---------------------------------------------------------------------------
__global__ __launch_bounds__(128) void attn_kernel(const int* __restrict__ mask)
{
    const int bh = blockIdx.y;
    const int b  = bh >> 4;             // H = 16
    const int q  = blockIdx.x * 128 + threadIdx.x;
    const int h  = bh & 15;

    const float4* Qrow  = (const float4*)(g_Q + (((size_t)bh)*LL + q)*HD);
    const float4* Kbase = (const float4*)(g_K + ((size_t)bh)*LL*HD);
    const float4* Vbase = (const float4*)(g_V + ((size_t)bh)*LL*HD);

    __shared__ float4 Ks[64*16];        // 64 keys x 64 floats
    __shared__ float4 Vs[64*16];
    __shared__ int    ms[64];

    float4 qv[16];
    #pragma unroll
    for (int i = 0; i < 16; i++) qv[i] = Qrow[i];

    float o[64];
    #pragma unroll
    for (int e = 0; e < 64; e++) o[e] = 0.f;
    float m = -1e30f, l = 0.f;

    for (int kt = 0; kt < LL/64; kt++) {
        __syncthreads();
        #pragma unroll
        for (int i = 0; i < 8; i++) {
            int idx = threadIdx.x + i*128;          // 1024 float4 per tile
            Ks[idx] = Kbase[kt*64*16 + idx];
            Vs[idx] = Vbase[kt*64*16 + idx];
        }
        if (threadIdx.x < 64) ms[threadIdx.x] = mask[b*LL + kt*64 + threadIdx.x];
        __syncthreads();

        for (int j = 0; j < 64; j++) {
            const float4* kr = &Ks[j*16];
            float s = 0.f;
            #pragma unroll
            for (int e = 0; e < 16; e++) {
                float4 kk = kr[e];
                s += qv[e].x*kk.x + qv[e].y*kk.y + qv[e].z*kk.z + qv[e].w*kk.w;
            }
            s *= 0.125f;                           // 1/sqrt(64)
            if (ms[j] == 0) s = -1e9f;

            if (s > m) {                           // lazy rescale (rare after warmup)
                float corr = __expf(m - s);
                l *= corr;
                #pragma unroll
                for (int e = 0; e < 64; e++) o[e] *= corr;
                m = s;
            }
            float p = __expf(s - m);
            l += p;
            const float4* vr = &Vs[j*16];
            #pragma unroll
            for (int e = 0; e < 16; e++) {
                float4 vv = vr[e];
                o[4*e+0] += p*vv.x; o[4*e+1] += p*vv.y;
                o[4*e+2] += p*vv.z; o[4*e+3] += p*vv.w;
            }
        }
    }

    const float inv = 1.0f / l;
    float* crow = g_CTX + ((size_t)(b*LL + q))*DD + h*HD;
    #pragma unroll
    for (int e = 0; e < 64; e++) crow[e] = o[e] * inv;
}

// ---------------------------------------------------------------------------
// Kernel 3: output projection. out = ctx @ Wo + bo.
// M=4096, N=1024, K=1024. Same 64x64/BK16 tiling as kernel 1.
// ---------------------------------------------------------------------------
__global__ __launch_bounds__(128) void out_proj_kernel(
    const float* __restrict__ Wo, const float* __restrict__ bo,
    float* __restrict__ out)
{
    __shared__ float As[16][65];
    __shared__ float Bs[16][64];

    const int tid = threadIdx.x;
    const int tx  = tid & 15;
    const int ty  = tid >> 4;
    const int row0 = blockIdx.x * 64;
    const int n0   = blockIdx.y * 64;

    float acc[8][4];
    #pragma unroll
    for (int i = 0; i < 8; i++)
        #pragma unroll
        for (int j = 0; j < 4; j++) acc[i][j] = 0.f;

    for (int k0 = 0; k0 < DD; k0 += 16) {
        #pragma unroll
        for (int i = 0; i < 2; i++) {
            int idx = tid + i*128;
            int r   = idx >> 2;
            int kc  = (idx & 3) * 4;
            float4 v = *(const float4*)&g_CTX[(size_t)(row0 + r)*DD + k0 + kc];
            As[kc+0][r] = v.x; As[kc+1][r] = v.y; As[kc+2][r] = v.z; As[kc+3][r] = v.w;
        }
        #pragma unroll
        for (int i = 0; i < 2; i++) {
            int idx = tid + i*128;
            int kr  = idx >> 4;
            int nc  = (idx & 15) * 4;
            *(float4*)&Bs[kr][nc] = *(const float4*)&Wo[(size_t)(k0 + kr)*DD + n0 + nc];
        }
        __syncthreads();
        #pragma unroll
        for (int kk = 0; kk < 16; kk++) {
            float a[8], bb[4];
            #pragma unroll
            for (int i = 0; i < 8; i++) a[i] = As[kk][ty*8 + i];
            #pragma unroll
            for (int j = 0; j < 4; j++) bb[j] = Bs[kk][tx*4 + j];
            #pragma unroll
            for (int i = 0; i < 8; i++)
                #pragma unroll
                for (int j = 0; j < 4; j++)
                    acc[i][j] += a[i] * bb[j];
        }
        __syncthreads();
    }

    #pragma unroll
    for (int i = 0; i < 8; i++) {
        int r = row0 + ty*8 + i;
        float* orow = out + (size_t)r*DD + n0;
        #pragma unroll
        for (int j = 0; j < 4; j++) {
            int n = tx*4 + j;
            orow[n] = acc[i][j] + bo[n0 + n];
        }
    }
}

// ---------------------------------------------------------------------------
extern "C" void kernel_launch(void* const* d_in, const int* in_sizes, int n_in,
                              void* d_out, int out_size)
{
    const float* x    = (const float*)d_in[0];
    const int*   mask = (const int*)  d_in[1];
    const float* Wq   = (const float*)d_in[2];
    const float* bq   = (const float*)d_in[3];
    const float* Wk   = (const float*)d_in[4];
    const float* bk   = (const float*)d_in[5];
    const float* Wv   = (const float*)d_in[6];
    const float* bv   = (const float*)d_in[7];
    const float* Wo   = (const float*)d_in[8];
    const float* bo   = (const float*)d_in[9];
    float* out = (float*)d_out;

    dim3 g1(BB*LL/64, HH, 3);            // (64, 16, 3)
    qkv_kernel<<<g1, 128>>>(x, Wq, bq, Wk, bk, Wv, bv);

    dim3 g2(LL/128, BB*HH);              // (16, 32)
    attn_kernel<<<g2, 128>>>(mask);

    dim3 g3(BB*LL/64, DD/64);            // (64, 16)
    out_proj_kernel<<<g3, 128>>>(Wo, bo, out);
}